// round 1
// baseline (speedup 1.0000x reference)
#include <cuda_runtime.h>
#include <math.h>

#define N_NODES 8192
#define F_IN    256
#define F_OUT   128

// Scratch (allocation-free rule: __device__ globals)
__device__ float g_Wh[N_NODES * F_OUT];   // 4 MB
__device__ float g_wh1[N_NODES];
__device__ float g_wh2[N_NODES];

// ---------------------------------------------------------------------------
// Kernel 1: Wh = h @ W   [8192,256] @ [256,128] -> [8192,128]
// Classic tiled SGEMM. BM=64, BN=128(full), BK=16, 256 thr, 4x8 microtile.
// ---------------------------------------------------------------------------
__global__ void __launch_bounds__(256) k1_gemm(const float* __restrict__ h,
                                               const float* __restrict__ W) {
    __shared__ float sA[16][64];    // [k][row]
    __shared__ float sB[16][128];   // [k][col]
    const int t  = threadIdx.x;
    const int ty = t >> 4;          // 0..15 -> rows ty*4..+4
    const int tx = t & 15;          // 0..15 -> cols tx*8..+8
    const int row0 = blockIdx.x * 64;

    float acc[4][8];
#pragma unroll
    for (int m = 0; m < 4; m++)
#pragma unroll
        for (int n = 0; n < 8; n++) acc[m][n] = 0.f;

    for (int k0 = 0; k0 < F_IN; k0 += 16) {
#pragma unroll
        for (int it = 0; it < 4; it++) {          // 64x16 A tile
            int idx = t + it * 256;
            int r = idx >> 4, kk = idx & 15;
            sA[kk][r] = h[(row0 + r) * F_IN + k0 + kk];
        }
#pragma unroll
        for (int it = 0; it < 8; it++) {          // 16x128 B tile
            int idx = t + it * 256;
            int kk = idx >> 7, c = idx & 127;
            sB[kk][c] = W[(k0 + kk) * F_OUT + c];
        }
        __syncthreads();
#pragma unroll
        for (int kk = 0; kk < 16; kk++) {
            float av[4], bv[8];
#pragma unroll
            for (int m = 0; m < 4; m++) av[m] = sA[kk][ty * 4 + m];
#pragma unroll
            for (int n = 0; n < 8; n++) bv[n] = sB[kk][tx * 8 + n];
#pragma unroll
            for (int m = 0; m < 4; m++)
#pragma unroll
                for (int n = 0; n < 8; n++) acc[m][n] += av[m] * bv[n];
        }
        __syncthreads();
    }
#pragma unroll
    for (int m = 0; m < 4; m++) {
        int r = row0 + ty * 4 + m;
#pragma unroll
        for (int n = 0; n < 8; n++)
            g_Wh[r * F_OUT + tx * 8 + n] = acc[m][n];
    }
}

// ---------------------------------------------------------------------------
// Kernel 2: wh1[i] = Wh[i,:] . a[0:128]; wh2[i] = Wh[i,:] . a[128:256]
// One warp per row.
// ---------------------------------------------------------------------------
__global__ void __launch_bounds__(256) k2_rowdots(const float* __restrict__ a) {
    int warp = threadIdx.x >> 5;
    int lane = threadIdx.x & 31;
    int row  = blockIdx.x * 8 + warp;
    float s1 = 0.f, s2 = 0.f;
#pragma unroll
    for (int q = 0; q < 4; q++) {
        int c = lane + q * 32;
        float v = g_Wh[row * F_OUT + c];
        s1 += v * a[c];
        s2 += v * a[F_OUT + c];
    }
#pragma unroll
    for (int off = 16; off > 0; off >>= 1) {
        s1 += __shfl_down_sync(0xffffffffu, s1, off);
        s2 += __shfl_down_sync(0xffffffffu, s2, off);
    }
    if (lane == 0) { g_wh1[row] = s1; g_wh2[row] = s2; }
}

// ---------------------------------------------------------------------------
// Kernel 3: fused masked-softmax attention + aggregate + ELU.
// Block = 64 output rows, 256 threads. Loop over j in chunks of 64.
// num_i = sum_j s_ij * Wh_j ; den_i = sum_j s_ij ; out = elu(num/den)
// s_ij = adj_ij>0 ? exp(leaky(wh1_i + wh2_j)) : 0   (no max-shift needed:
// scores ~ N(0,1), max ~ 6 -> exp safe in fp32)
// ---------------------------------------------------------------------------
#define BM 64
#define BK 64
#define SS_STRIDE 65

__global__ void __launch_bounds__(256, 1)
k3_attn(const int* __restrict__ adj, float* __restrict__ out) {
    extern __shared__ float sm[];
    float* sWh  = sm;                       // [BK][128]     8192 f
    float* sS   = sWh + BK * F_OUT;         // [BM][65]      4160 f
    float* sWh2 = sS + BM * SS_STRIDE;      // 64
    float* sWh1 = sWh2 + BM;                // 64
    float* sDen = sWh1 + BM;                // 64

    const int t  = threadIdx.x;
    const int ty = t >> 4;                  // rows ty*4..+4
    const int tx = t & 15;                  // cols tx*8..+8
    const int row0 = blockIdx.x * BM;

    if (t < BM) sWh1[t] = g_wh1[row0 + t];

    float acc[4][8];
#pragma unroll
    for (int m = 0; m < 4; m++)
#pragma unroll
        for (int n = 0; n < 8; n++) acc[m][n] = 0.f;
    float den[4] = {0.f, 0.f, 0.f, 0.f};

    const int cB = t & 63;                  // stage-B column within chunk
    const int rB = t >> 6;                  // stage-B row base (0..3)

    for (int j0 = 0; j0 < N_NODES; j0 += BK) {
        __syncthreads();   // protect sWh/sS from previous chunk's stage C

        // Stage A: load Wh chunk (contiguous 8192 floats) + wh2 chunk
        {
            const float4* src = (const float4*)(g_Wh + j0 * F_OUT);
            float4* dst = (float4*)sWh;
#pragma unroll
            for (int it = 0; it < 8; it++) dst[t + it * 256] = src[t + it * 256];
            if (t < BK) sWh2[t] = g_wh2[j0 + t];
        }
        __syncthreads();

        // Stage B: score tile s[BM][BK]
#pragma unroll
        for (int it = 0; it < 16; it++) {
            int r = rB + it * 4;
            float e = sWh1[r] + sWh2[cB];
            e = fmaxf(e, 0.2f * e);                    // LeakyReLU(0.2)
            int av = adj[(long)(row0 + r) * N_NODES + j0 + cB];
            sS[r * SS_STRIDE + cB] = (av > 0) ? __expf(e) : 0.f;
        }
        __syncthreads();

        // Stage C: acc += s @ WhChunk ; den += row-sum(s)
#pragma unroll 4
        for (int jj = 0; jj < BK; jj++) {
            float4 b0 = *(const float4*)&sWh[jj * F_OUT + tx * 8];
            float4 b1 = *(const float4*)&sWh[jj * F_OUT + tx * 8 + 4];
#pragma unroll
            for (int m = 0; m < 4; m++) {
                float s = sS[(ty * 4 + m) * SS_STRIDE + jj];
                den[m] += s;
                acc[m][0] += s * b0.x; acc[m][1] += s * b0.y;
                acc[m][2] += s * b0.z; acc[m][3] += s * b0.w;
                acc[m][4] += s * b1.x; acc[m][5] += s * b1.y;
                acc[m][6] += s * b1.z; acc[m][7] += s * b1.w;
            }
        }
    }

    // den is replicated across tx groups; tx==0's copy is authoritative
    if (tx == 0) {
#pragma unroll
        for (int m = 0; m < 4; m++) sDen[ty * 4 + m] = den[m];
    }
    __syncthreads();

#pragma unroll
    for (int m = 0; m < 4; m++) {
        int r = ty * 4 + m;
        float inv = 1.0f / sDen[r];
#pragma unroll
        for (int n = 0; n < 8; n++) {
            float v = acc[m][n] * inv;
            v = (v > 0.f) ? v : expm1f(v);             // ELU(alpha=1)
            out[(row0 + r) * F_OUT + tx * 8 + n] = v;
        }
    }
}

// ---------------------------------------------------------------------------
extern "C" void kernel_launch(void* const* d_in, const int* in_sizes, int n_in,
                              void* d_out, int out_size) {
    const float* h   = (const float*)d_in[0];
    const int*   adj = (const int*)  d_in[1];
    const float* W   = (const float*)d_in[2];
    const float* a   = (const float*)d_in[3];
    float* out = (float*)d_out;

    const int smem3 = (BK * F_OUT + BM * SS_STRIDE + 3 * BM) * sizeof(float);
    cudaFuncSetAttribute(k3_attn, cudaFuncAttributeMaxDynamicSharedMemorySize, smem3);

    k1_gemm<<<N_NODES / 64, 256>>>(h, W);
    k2_rowdots<<<N_NODES / 8, 256>>>(a);
    k3_attn<<<N_NODES / BM, 256, smem3>>>(adj, out);
}

// round 3
// speedup vs baseline: 2.8821x; 2.8821x over previous
#include <cuda_runtime.h>
#include <cuda_bf16.h>
#include <stdint.h>
#include <math.h>

#define N_NODES 8192
#define F_IN    256
#define F_OUT   128

// ---------------- scratch (__device__ globals: allocation-free rule) --------
__device__ float g_Wh[N_NODES * F_OUT];                  // 4 MB
__device__ float g_wh1[N_NODES];
__device__ float g_wh2[N_NODES];
__device__ __nv_bfloat16 g_WhT_hi[F_OUT * N_NODES];      // 2 MB  [c][j]
__device__ __nv_bfloat16 g_WhT_lo[F_OUT * N_NODES];      // 2 MB  [c][j]
__device__ float g_part[2][N_NODES * F_OUT];             // 8 MB partial numerators
__device__ float g_denp[2][N_NODES];                     // partial denominators

// ---------------- helpers ---------------------------------------------------
__device__ __forceinline__ uint32_t smem_u32(const void* p) {
    uint32_t a;
    asm("{ .reg .u64 t; cvta.to.shared.u64 t, %1; cvt.u32.u64 %0, t; }"
        : "=r"(a) : "l"(p));
    return a;
}
__device__ __forceinline__ void ldsm4(uint32_t* r, uint32_t addr) {
    asm volatile("ldmatrix.sync.aligned.m8n8.x4.shared.b16 {%0,%1,%2,%3}, [%4];"
                 : "=r"(r[0]), "=r"(r[1]), "=r"(r[2]), "=r"(r[3]) : "r"(addr));
}
__device__ __forceinline__ void mma16816(float* d, const uint32_t* a,
                                         const uint32_t* b) {
    asm volatile(
        "mma.sync.aligned.m16n8k16.row.col.f32.bf16.bf16.f32 "
        "{%0,%1,%2,%3}, {%4,%5,%6,%7}, {%8,%9}, {%0,%1,%2,%3};"
        : "+f"(d[0]), "+f"(d[1]), "+f"(d[2]), "+f"(d[3])
        : "r"(a[0]), "r"(a[1]), "r"(a[2]), "r"(a[3]), "r"(b[0]), "r"(b[1]));
}
// pack two floats -> bf16x2 (first arg = low half)
__device__ __forceinline__ uint32_t pack2(float lo, float hi) {
    uint32_t r;
    asm("cvt.rn.bf16x2.f32 %0, %1, %2;" : "=r"(r) : "f"(hi), "f"(lo));
    return r;
}

// ---------------------------------------------------------------------------
// k1: Wh = h @ W ; fused epilogue computes wh1 = Wh.a1, wh2 = Wh.a2
// ---------------------------------------------------------------------------
__global__ void __launch_bounds__(256) k1_gemm(const float* __restrict__ h,
                                               const float* __restrict__ W,
                                               const float* __restrict__ a) {
    __shared__ float sA[16][64];
    __shared__ float sB[16][128];
    const int t  = threadIdx.x;
    const int ty = t >> 4;
    const int tx = t & 15;
    const int row0 = blockIdx.x * 64;

    float acc[4][8];
#pragma unroll
    for (int m = 0; m < 4; m++)
#pragma unroll
        for (int n = 0; n < 8; n++) acc[m][n] = 0.f;

    for (int k0 = 0; k0 < F_IN; k0 += 16) {
#pragma unroll
        for (int it = 0; it < 4; it++) {
            int idx = t + it * 256;
            int r = idx >> 4, kk = idx & 15;
            sA[kk][r] = h[(row0 + r) * F_IN + k0 + kk];
        }
#pragma unroll
        for (int it = 0; it < 8; it++) {
            int idx = t + it * 256;
            int kk = idx >> 7, c = idx & 127;
            sB[kk][c] = W[(k0 + kk) * F_OUT + c];
        }
        __syncthreads();
#pragma unroll
        for (int kk = 0; kk < 16; kk++) {
            float av[4], bv[8];
#pragma unroll
            for (int m = 0; m < 4; m++) av[m] = sA[kk][ty * 4 + m];
#pragma unroll
            for (int n = 0; n < 8; n++) bv[n] = sB[kk][tx * 8 + n];
#pragma unroll
            for (int m = 0; m < 4; m++)
#pragma unroll
                for (int n = 0; n < 8; n++) acc[m][n] += av[m] * bv[n];
        }
        __syncthreads();
    }
    float a1v[8], a2v[8];
#pragma unroll
    for (int n = 0; n < 8; n++) {
        a1v[n] = a[tx * 8 + n];
        a2v[n] = a[F_OUT + tx * 8 + n];
    }
#pragma unroll
    for (int m = 0; m < 4; m++) {
        int r = row0 + ty * 4 + m;
#pragma unroll
        for (int n = 0; n < 8; n++)
            g_Wh[r * F_OUT + tx * 8 + n] = acc[m][n];
        float p1 = 0.f, p2 = 0.f;
#pragma unroll
        for (int n = 0; n < 8; n++) {
            p1 += acc[m][n] * a1v[n];
            p2 += acc[m][n] * a2v[n];
        }
#pragma unroll
        for (int off = 8; off > 0; off >>= 1) {
            p1 += __shfl_down_sync(0xffffffffu, p1, off);
            p2 += __shfl_down_sync(0xffffffffu, p2, off);
        }
        if (tx == 0) { g_wh1[r] = p1; g_wh2[r] = p2; }
    }
}

// ---------------------------------------------------------------------------
// k2: transpose Wh -> WhT and split fp32 = bf16_hi + bf16_lo
// ---------------------------------------------------------------------------
__global__ void __launch_bounds__(256) k2_transpose() {
    __shared__ float tile[32][33];
    const int tx = threadIdx.x & 31;
    const int ty = threadIdx.x >> 5;
    const int nb = blockIdx.x * 32;
    const int fb = blockIdx.y * 32;
#pragma unroll
    for (int rr = ty; rr < 32; rr += 8)
        tile[rr][tx] = g_Wh[(nb + rr) * F_OUT + fb + tx];
    __syncthreads();
#pragma unroll
    for (int rr = ty; rr < 32; rr += 8) {
        float v = tile[tx][rr];
        __nv_bfloat16 hb = __float2bfloat16(v);
        float hf = __bfloat162float(hb);
        __nv_bfloat16 lb = __float2bfloat16(v - hf);
        size_t o = (size_t)(fb + rr) * N_NODES + nb + tx;
        g_WhT_hi[o] = hb;
        g_WhT_lo[o] = lb;
    }
}

// ---------------------------------------------------------------------------
// k3: fused masked-softmax attention on mma.sync (bf16 3-pass split)
// grid = 128 = 64 row-blocks x 2 j-splits; BM=128, BK=128 per chunk
// SMEM tiles padded to 272B rows: 272 mod 128 = 16 -> ldmatrix conflict-free.
// ---------------------------------------------------------------------------
#define BK 128
#define NCHUNK 32
#define TSTRIDE 272                       // bytes per tile row (128*2 + 16)
#define TILE_BYTES (128 * TSTRIDE)        // 34816
#define OFF_SHI  0
#define OFF_SLO  (OFF_SHI + TILE_BYTES)
#define OFF_BHI  (OFF_SLO + TILE_BYTES)
#define OFF_BLO  (OFF_BHI + TILE_BYTES)
#define OFF_WH2  (OFF_BLO + TILE_BYTES)
#define SMEM3    (OFF_WH2 + 4096 * 4)     // 155,648 B

__global__ void __launch_bounds__(256, 1)
k3_attn(const int* __restrict__ adj) {
    extern __shared__ __align__(128) char sm[];
    const uint32_t sbase = smem_u32(sm);
    const int t   = threadIdx.x;
    const int wid = t >> 5;
    const int lid = t & 31;
    const int rb    = blockIdx.x >> 1;
    const int split = blockIdx.x & 1;
    const int row0  = rb * 128;
    const int jg0   = split * 4096;

    float* sWh2 = (float*)(sm + OFF_WH2);
#pragma unroll
    for (int i = 0; i < 16; i++)
        sWh2[t + i * 256] = g_wh2[jg0 + t + i * 256];

    // ---- generation-stage mapping: thread -> (row r, j-half) ----
    const int r    = t >> 1;
    const int half = t & 1;
    const int jb   = half * 64;
    const float wh1r = g_wh1[row0 + r];
    float den = 0.f;

    const __nv_bfloat16* srcHi = g_WhT_hi + (size_t)r * N_NODES + jg0 + jb;
    const __nv_bfloat16* srcLo = g_WhT_lo + (size_t)r * N_NODES + jg0 + jb;
    const int* adjp = adj + (size_t)(row0 + r) * N_NODES + jg0 + jb;
    const uint32_t genRow = (uint32_t)r * TSTRIDE;

    // ---- mma-stage mapping: 8 warps = 2(m) x 4(n); warp tile 64x32 ----
    const int warp_m = wid >> 2;
    const int warp_n = wid & 3;
    float d[4][4][4];
#pragma unroll
    for (int mf = 0; mf < 4; mf++)
#pragma unroll
        for (int nf = 0; nf < 4; nf++)
#pragma unroll
            for (int q = 0; q < 4; q++) d[mf][nf][q] = 0.f;

    // ldmatrix per-lane address components
    const int g = lid >> 3;
    const uint32_t aLane = (uint32_t)((g & 1) * 8 + (lid & 7)) * TSTRIDE
                         + (uint32_t)((g >> 1) * 8) * 2;
    const uint32_t bLane = (uint32_t)((g >> 1) * 8 + (lid & 7)) * TSTRIDE
                         + (uint32_t)((g & 1) * 8) * 2;
    const uint32_t aBase = sbase + (uint32_t)(warp_m * 64) * TSTRIDE + aLane;
    const uint32_t bBase = sbase + (uint32_t)(warp_n * 32) * TSTRIDE + bLane;

    __syncthreads();

    for (int c = 0; c < NCHUNK; c++) {
        // ---- Stage A: B tiles (WhT hi/lo) + S tiles (scores hi/lo) ----
#pragma unroll
        for (int kk = 0; kk < 8; kk++) {
            uint4 vh = *(const uint4*)(srcHi + (size_t)c * BK + kk * 8);
            uint4 vl = *(const uint4*)(srcLo + (size_t)c * BK + kk * 8);
            uint32_t o = genRow + (uint32_t)(jb + kk * 8) * 2;
            *(uint4*)(sm + OFF_BHI + o) = vh;
            *(uint4*)(sm + OFF_BLO + o) = vl;
        }
#pragma unroll
        for (int kk = 0; kk < 16; kk++) {
            int4 av = *(const int4*)(adjp + (size_t)c * BK + kk * 4);
            int jl = jb + kk * 4;
            float w0 = sWh2[c * BK + jl + 0], w1 = sWh2[c * BK + jl + 1];
            float w2 = sWh2[c * BK + jl + 2], w3 = sWh2[c * BK + jl + 3];
            float e0 = wh1r + w0, e1 = wh1r + w1, e2 = wh1r + w2, e3 = wh1r + w3;
            e0 = fmaxf(e0, 0.2f * e0); e1 = fmaxf(e1, 0.2f * e1);
            e2 = fmaxf(e2, 0.2f * e2); e3 = fmaxf(e3, 0.2f * e3);
            float s0 = (av.x > 0) ? __expf(e0) : 0.f;
            float s1 = (av.y > 0) ? __expf(e1) : 0.f;
            float s2 = (av.z > 0) ? __expf(e2) : 0.f;
            float s3 = (av.w > 0) ? __expf(e3) : 0.f;
            den += (s0 + s1) + (s2 + s3);
            uint32_t h01 = pack2(s0, s1), h23 = pack2(s2, s3);
            float f0 = __uint_as_float(h01 << 16);
            float f1 = __uint_as_float(h01 & 0xFFFF0000u);
            float f2 = __uint_as_float(h23 << 16);
            float f3 = __uint_as_float(h23 & 0xFFFF0000u);
            uint32_t l01 = pack2(s0 - f0, s1 - f1);
            uint32_t l23 = pack2(s2 - f2, s3 - f3);
            uint32_t o = genRow + (uint32_t)jl * 2;
            *(uint2*)(sm + OFF_SHI + o) = make_uint2(h01, h23);
            *(uint2*)(sm + OFF_SLO + o) = make_uint2(l01, l23);
        }
        __syncthreads();

        // ---- Stage B: D += Shi*Bhi + Shi*Blo + Slo*Bhi ----
#pragma unroll
        for (int ks = 0; ks < 8; ks++) {
            uint32_t ahi[4][4], alo[4][4], bhi[2][4], blo[2][4];
#pragma unroll
            for (int mf = 0; mf < 4; mf++) {
                uint32_t ad = aBase + (uint32_t)(mf * 16) * TSTRIDE + ks * 32;
                ldsm4(ahi[mf], ad + OFF_SHI);
                ldsm4(alo[mf], ad + OFF_SLO);
            }
#pragma unroll
            for (int nf2 = 0; nf2 < 2; nf2++) {
                uint32_t bd = bBase + (uint32_t)(nf2 * 16) * TSTRIDE + ks * 32;
                ldsm4(bhi[nf2], bd + OFF_BHI);
                ldsm4(blo[nf2], bd + OFF_BLO);
            }
#pragma unroll
            for (int mf = 0; mf < 4; mf++)
#pragma unroll
                for (int nf = 0; nf < 4; nf++)
                    mma16816(d[mf][nf], ahi[mf], &bhi[nf >> 1][(nf & 1) * 2]);
#pragma unroll
            for (int mf = 0; mf < 4; mf++)
#pragma unroll
                for (int nf = 0; nf < 4; nf++)
                    mma16816(d[mf][nf], ahi[mf], &blo[nf >> 1][(nf & 1) * 2]);
#pragma unroll
            for (int mf = 0; mf < 4; mf++)
#pragma unroll
                for (int nf = 0; nf < 4; nf++)
                    mma16816(d[mf][nf], alo[mf], &bhi[nf >> 1][(nf & 1) * 2]);
        }
        __syncthreads();
    }

    // ---- partial denominator (combine j-halves within lane pair) ----
    float dsum = den + __shfl_xor_sync(0xffffffffu, den, 1);
    if (half == 0) g_denp[split][row0 + r] = dsum;

    // ---- partial numerator: register tiles -> g_part ----
    const int qr = lid >> 2;             // 0..7
    const int qc = (lid & 3) * 2;
    float* base = g_part[split] + (size_t)(row0 + warp_m * 64 + qr) * F_OUT
                + warp_n * 32 + qc;
#pragma unroll
    for (int mf = 0; mf < 4; mf++) {
#pragma unroll
        for (int nf = 0; nf < 4; nf++) {
            float* p = base + (size_t)(mf * 16) * F_OUT + nf * 8;
            *(float2*)p = make_float2(d[mf][nf][0], d[mf][nf][1]);
            *(float2*)(p + 8 * F_OUT) = make_float2(d[mf][nf][2], d[mf][nf][3]);
        }
    }
}

// ---------------------------------------------------------------------------
// k4: combine splits, divide, ELU
// ---------------------------------------------------------------------------
__global__ void __launch_bounds__(256) k4_combine(float* __restrict__ out) {
    int tid = blockIdx.x * 256 + threadIdx.x;
    int e = tid * 8;
    int row = e >> 7;
    float dinv = 1.0f / (g_denp[0][row] + g_denp[1][row]);
    const float4* p0 = (const float4*)(g_part[0] + e);
    const float4* p1 = (const float4*)(g_part[1] + e);
    float4* o = (float4*)(out + e);
#pragma unroll
    for (int q = 0; q < 2; q++) {
        float4 x = p0[q], y = p1[q];
        float v0 = (x.x + y.x) * dinv;
        float v1 = (x.y + y.y) * dinv;
        float v2 = (x.z + y.z) * dinv;
        float v3 = (x.w + y.w) * dinv;
        float4 r;
        r.x = (v0 > 0.f) ? v0 : expm1f(v0);
        r.y = (v1 > 0.f) ? v1 : expm1f(v1);
        r.z = (v2 > 0.f) ? v2 : expm1f(v2);
        r.w = (v3 > 0.f) ? v3 : expm1f(v3);
        o[q] = r;
    }
}

// ---------------------------------------------------------------------------
extern "C" void kernel_launch(void* const* d_in, const int* in_sizes, int n_in,
                              void* d_out, int out_size) {
    const float* h   = (const float*)d_in[0];
    const int*   adj = (const int*)  d_in[1];
    const float* W   = (const float*)d_in[2];
    const float* a   = (const float*)d_in[3];
    float* out = (float*)d_out;

    cudaFuncSetAttribute(k3_attn, cudaFuncAttributeMaxDynamicSharedMemorySize, SMEM3);

    k1_gemm<<<N_NODES / 64, 256>>>(h, W, a);
    k2_transpose<<<dim3(N_NODES / 32, F_OUT / 32), 256>>>();
    k3_attn<<<128, 256, SMEM3>>>(adj);
    k4_combine<<<512, 256>>>(out);
}